// round 2
// baseline (speedup 1.0000x reference)
#include <cuda_runtime.h>
#include <cstdint>

#define LDIM 2048
#define BDIM 32
#define DDIM 512
#define MDIM (LDIM * BDIM)   // 65536
#define NDIM (DDIM * 3)      // 1536
#define KDIM DDIM            // 512

// Scratch: three SoA planes U0,U1,U2, each [M][D] fp32 (3 * 128 MB)
__device__ float g_U[3ULL * MDIM * DDIM];

// ---------------------------------------------------------------------------
// GEMM: U[m][o] = sum_k x[m][k] * W[k][o],  o = 3*d + j  ->  plane j, col d
// 128x128x16 tiles, double-buffered smem, 256 threads, 8x8 per thread.
// ---------------------------------------------------------------------------
#define BM 128
#define BN 128
#define BK 16

__global__ __launch_bounds__(256, 2)
void sru_gemm_kernel(const float* __restrict__ A, const float* __restrict__ B)
{
    __shared__ float As[2][BK][BM];
    __shared__ float Bs[2][BK][BN];

    const int tid = threadIdx.x;
    const int m0 = blockIdx.y * BM;
    const int n0 = blockIdx.x * BN;

    // A tile loads: 128x16 floats = 512 float4; thread -> (row=tid/4, col4=tid%4), rows +0,+64
    const int arow = tid >> 2;          // 0..63
    const int acol = (tid & 3) * 4;     // 0,4,8,12
    // B tile loads: 16x128 floats = 512 float4; thread -> (row=tid/32, col4=tid%32), rows +0,+8
    const int brow = tid >> 5;          // 0..7
    const int bcol = (tid & 31) * 4;

    const float* Aptr = A + (size_t)(m0 + arow) * KDIM + acol;
    const float* Bptr = B + (size_t)brow * NDIM + n0 + bcol;

    float acc[8][8];
#pragma unroll
    for (int i = 0; i < 8; i++)
#pragma unroll
        for (int j = 0; j < 8; j++) acc[i][j] = 0.f;

    // Load tile 0
    {
        float4 a0 = *(const float4*)(Aptr);
        float4 a1 = *(const float4*)(Aptr + 64 * KDIM);
        As[0][acol + 0][arow] = a0.x; As[0][acol + 1][arow] = a0.y;
        As[0][acol + 2][arow] = a0.z; As[0][acol + 3][arow] = a0.w;
        As[0][acol + 0][arow + 64] = a1.x; As[0][acol + 1][arow + 64] = a1.y;
        As[0][acol + 2][arow + 64] = a1.z; As[0][acol + 3][arow + 64] = a1.w;
        *(float4*)&Bs[0][brow][bcol]     = *(const float4*)(Bptr);
        *(float4*)&Bs[0][brow + 8][bcol] = *(const float4*)(Bptr + 8 * NDIM);
    }
    __syncthreads();

    const int rm = (tid >> 4) * 8;   // 0..120
    const int rn = (tid & 15) * 8;   // 0..120

    int buf = 0;
    const int NK = KDIM / BK;        // 32
    for (int kt = 0; kt < NK; kt++) {
        float4 na0, na1, nb0, nb1;
        const bool more = (kt + 1 < NK);
        if (more) {
            const float* Ap = Aptr + (kt + 1) * BK;
            na0 = *(const float4*)(Ap);
            na1 = *(const float4*)(Ap + 64 * KDIM);
            const float* Bp = Bptr + (size_t)(kt + 1) * BK * NDIM;
            nb0 = *(const float4*)(Bp);
            nb1 = *(const float4*)(Bp + 8 * NDIM);
        }
#pragma unroll
        for (int k = 0; k < BK; k++) {
            float a[8], b[8];
            *(float4*)&a[0] = *(const float4*)&As[buf][k][rm];
            *(float4*)&a[4] = *(const float4*)&As[buf][k][rm + 4];
            *(float4*)&b[0] = *(const float4*)&Bs[buf][k][rn];
            *(float4*)&b[4] = *(const float4*)&Bs[buf][k][rn + 4];
#pragma unroll
            for (int i = 0; i < 8; i++)
#pragma unroll
                for (int j = 0; j < 8; j++)
                    acc[i][j] = fmaf(a[i], b[j], acc[i][j]);
        }
        if (more) {
            const int nb = buf ^ 1;
            As[nb][acol + 0][arow] = na0.x; As[nb][acol + 1][arow] = na0.y;
            As[nb][acol + 2][arow] = na0.z; As[nb][acol + 3][arow] = na0.w;
            As[nb][acol + 0][arow + 64] = na1.x; As[nb][acol + 1][arow + 64] = na1.y;
            As[nb][acol + 2][arow + 64] = na1.z; As[nb][acol + 3][arow + 64] = na1.w;
            *(float4*)&Bs[nb][brow][bcol]     = nb0;
            *(float4*)&Bs[nb][brow + 8][bcol] = nb1;
        }
        __syncthreads();
        buf ^= 1;
    }

    // Epilogue: scatter into SoA planes. o = n0+rn+j -> plane (o%3), col (o/3)
    const size_t plane = (size_t)MDIM * DDIM;
#pragma unroll
    for (int i = 0; i < 8; i++) {
        const size_t mrow = (size_t)(m0 + rm + i) * DDIM;
#pragma unroll
        for (int j = 0; j < 8; j++) {
            const int o = n0 + rn + j;
            const int jp = o % 3;
            const int dd = o / 3;
            g_U[(size_t)jp * plane + mrow + dd] = acc[i][j];
        }
    }
}

// ---------------------------------------------------------------------------
// Scan: one thread per (b,d) channel, sequential over L with 8-deep
// double-buffered register prefetch of (u0,u1,u2,x).
// ---------------------------------------------------------------------------
__device__ __forceinline__ float sigmoidf_fast(float z)
{
    return __fdividef(1.f, 1.f + __expf(-z));
}

__global__ __launch_bounds__(128)
void sru_scan_kernel(const float* __restrict__ x,
                     const float* __restrict__ wc,
                     const float* __restrict__ bias,
                     float* __restrict__ out)
{
    const int tid = blockIdx.x * 128 + threadIdx.x;   // 0..16383 = b*D + d
    const int d = tid & (DDIM - 1);

    const float wcf = wc[d];
    const float wcr = wc[DDIM + d];
    const float bf = bias[d];
    const float br = bias[DDIM + d];

    const size_t plane = (size_t)MDIM * DDIM;
    const float* __restrict__ U0 = g_U;
    const float* __restrict__ U1 = g_U + plane;
    const float* __restrict__ U2 = g_U + 2 * plane;

    const size_t stride = (size_t)BDIM * DDIM;   // 16384
    float c = 0.f;

    const int P = 8;
    float pu0[P], pu1[P], pu2[P], px[P];
#pragma unroll
    for (int i = 0; i < P; i++) {
        const size_t a = (size_t)tid + (size_t)i * stride;
        pu0[i] = U0[a]; pu1[i] = U1[a]; pu2[i] = U2[a]; px[i] = x[a];
    }

    for (int l0 = 0; l0 < LDIM; l0 += P) {
        float nu0[P], nu1[P], nu2[P], nx[P];
        const bool more = (l0 + P < LDIM);
        if (more) {
            const size_t nb = (size_t)tid + (size_t)(l0 + P) * stride;
#pragma unroll
            for (int i = 0; i < P; i++) {
                const size_t a = nb + (size_t)i * stride;
                nu0[i] = U0[a]; nu1[i] = U1[a]; nu2[i] = U2[a]; nx[i] = x[a];
            }
        }
#pragma unroll
        for (int i = 0; i < P; i++) {
            const float zf = fmaf(wcf, c, pu1[i] + bf);
            const float fg = sigmoidf_fast(zf);
            const float zr = fmaf(wcr, c, pu2[i] + br);
            const float rg = sigmoidf_fast(zr);
            c = fmaf(fg, c - pu0[i], pu0[i]);          // fg*c + (1-fg)*u0
            const float h = fmaf(rg, c - px[i], px[i]); // rg*c + (1-rg)*x
            out[(size_t)tid + (size_t)(l0 + i) * stride] = h;
        }
        if (more) {
#pragma unroll
            for (int i = 0; i < P; i++) {
                pu0[i] = nu0[i]; pu1[i] = nu1[i]; pu2[i] = nu2[i]; px[i] = nx[i];
            }
        }
    }

    // c_last appended after h
    out[(size_t)LDIM * stride + tid] = c;
}

// ---------------------------------------------------------------------------
extern "C" void kernel_launch(void* const* d_in, const int* in_sizes, int n_in,
                              void* d_out, int out_size)
{
    const float* x    = (const float*)d_in[0];   // (L,B,D)
    const float* W    = (const float*)d_in[1];   // (D, 3D)
    const float* wc   = (const float*)d_in[2];   // (2D,)
    const float* bias = (const float*)d_in[3];   // (2D,)
    float* out = (float*)d_out;                  // h (L,B,D) then c_last (B,D)

    dim3 ggrid(NDIM / BN, MDIM / BM);            // (12, 512)
    sru_gemm_kernel<<<ggrid, 256>>>(x, W);
    sru_scan_kernel<<<MDIM * DDIM / DDIM / 128 * 0 + (BDIM * DDIM / 128), 128>>>(x, wc, bias, out);
}

// round 4
// speedup vs baseline: 1.6591x; 1.6591x over previous
#include <cuda_runtime.h>
#include <cuda_bf16.h>
#include <cstdint>

#define LDIM 2048
#define BDIM 32
#define DDIM 512
#define MDIM (LDIM * BDIM)   // 65536
#define NDIM (DDIM * 3)      // 1536
#define KDIM DDIM            // 512

// ---------------------------------------------------------------------------
// Device scratch
// ---------------------------------------------------------------------------
__device__ float          g_U[(size_t)MDIM * NDIM];    // U interleaved [m][3d+j]
__device__ __nv_bfloat16  g_Ahi[(size_t)MDIM * KDIM];
__device__ __nv_bfloat16  g_Alo[(size_t)MDIM * KDIM];
__device__ __nv_bfloat16  g_Bhi[(size_t)NDIM * KDIM];  // W^T hi [o][k]
__device__ __nv_bfloat16  g_Blo[(size_t)NDIM * KDIM];  // W^T lo [o][k]

__device__ __forceinline__ uint32_t smem_u32(const void* p) {
    uint32_t a;
    asm("{ .reg .u64 t; cvta.to.shared.u64 t, %1; cvt.u32.u64 %0, t; }" : "=r"(a) : "l"(p));
    return a;
}
#define SW128(o) ((o) ^ (((o) >> 3) & 0x70))

__device__ __forceinline__ void cp_async16(uint32_t saddr, const void* gaddr) {
    asm volatile("cp.async.cg.shared.global [%0], [%1], 16;" :: "r"(saddr), "l"(gaddr) : "memory");
}
#define CP_COMMIT() asm volatile("cp.async.commit_group;" ::: "memory")
#define CP_WAIT(n)  asm volatile("cp.async.wait_group %0;" :: "n"(n) : "memory")

__device__ __forceinline__ void ldsm_x4(uint32_t& r0, uint32_t& r1, uint32_t& r2, uint32_t& r3, uint32_t addr) {
    asm volatile("ldmatrix.sync.aligned.m8n8.x4.shared.b16 {%0,%1,%2,%3}, [%4];"
                 : "=r"(r0), "=r"(r1), "=r"(r2), "=r"(r3) : "r"(addr));
}
__device__ __forceinline__ void mma_bf16(float& c0, float& c1, float& c2, float& c3,
                                         uint32_t a0, uint32_t a1, uint32_t a2, uint32_t a3,
                                         uint32_t b0, uint32_t b1) {
    asm volatile("mma.sync.aligned.m16n8k16.row.col.f32.bf16.bf16.f32 "
                 "{%0,%1,%2,%3}, {%4,%5,%6,%7}, {%8,%9}, {%0,%1,%2,%3};"
                 : "+f"(c0), "+f"(c1), "+f"(c2), "+f"(c3)
                 : "r"(a0), "r"(a1), "r"(a2), "r"(a3), "r"(b0), "r"(b1));
}

// ---------------------------------------------------------------------------
// Converts
// ---------------------------------------------------------------------------
__global__ __launch_bounds__(256)
void convert_x_kernel(const float* __restrict__ x)
{
    const size_t i = (size_t)blockIdx.x * 256 + threadIdx.x;   // float4 index
    const float4 v = ((const float4*)x)[i];
    float f[4] = {v.x, v.y, v.z, v.w};
    __nv_bfloat16 h[4], l[4];
#pragma unroll
    for (int j = 0; j < 4; j++) {
        h[j] = __float2bfloat16(f[j]);
        l[j] = __float2bfloat16(f[j] - __bfloat162float(h[j]));
    }
    __nv_bfloat162* ph = (__nv_bfloat162*)g_Ahi;
    __nv_bfloat162* pl = (__nv_bfloat162*)g_Alo;
    ph[2*i]   = __nv_bfloat162(h[0], h[1]);
    ph[2*i+1] = __nv_bfloat162(h[2], h[3]);
    pl[2*i]   = __nv_bfloat162(l[0], l[1]);
    pl[2*i+1] = __nv_bfloat162(l[2], l[3]);
}

__global__ __launch_bounds__(256)
void convert_w_kernel(const float* __restrict__ W)
{
    const int idx = blockIdx.x * 256 + threadIdx.x;   // < KDIM*NDIM
    const int k = idx / NDIM;
    const int o = idx % NDIM;
    const float f = W[idx];
    const __nv_bfloat16 h = __float2bfloat16(f);
    const __nv_bfloat16 l = __float2bfloat16(f - __bfloat162float(h));
    g_Bhi[(size_t)o * KDIM + k] = h;
    g_Blo[(size_t)o * KDIM + k] = l;
}

// ---------------------------------------------------------------------------
// bf16 HMMA GEMM (3-term split), 128x128x64 tiles, cp.async 2-stage pipeline.
// ---------------------------------------------------------------------------
#define BK 64
#define NSTG (KDIM / BK)            // 8
#define BUF_B (128 * BK * 2)        // 16384 bytes per operand buffer
#define STAGE_B (4 * BUF_B)         // Ah, Al, Bh, Bl
#define GSMEM (2 * STAGE_B)         // 131072
#define EPAD 132                    // epilogue stage row stride (floats)

__global__ __launch_bounds__(256, 1)
void sru_gemm_hmma()
{
    extern __shared__ char smem[];
    const uint32_t sbase = smem_u32(smem);
    const int tid = threadIdx.x;
    const int n0 = blockIdx.x * 128;
    const int m0 = blockIdx.y * 128;

    const int wid = tid >> 5;
    const int lane = tid & 31;
    const int wm0 = (wid & 1) * 64;     // warp m offset
    const int wn0 = (wid >> 1) * 32;    // warp n offset

    // ---- stage loader: 4 buffers x 1024 uint4 slots; thread does 4 per buffer
    auto load_stage = [&](int stg, int c) {
        const uint32_t sb = sbase + (uint32_t)(stg * STAGE_B);
        const int k0 = c * BK;
        const __nv_bfloat16* srcs[4] = {
            g_Ahi + (size_t)m0 * KDIM + k0,
            g_Alo + (size_t)m0 * KDIM + k0,
            g_Bhi + (size_t)n0 * KDIM + k0,
            g_Blo + (size_t)n0 * KDIM + k0,
        };
#pragma unroll
        for (int b = 0; b < 4; ++b) {
#pragma unroll
            for (int j = 0; j < 4; ++j) {
                const int slot = j * 256 + tid;    // 0..1023
                const int row  = slot >> 3;
                const int kb   = slot & 7;
                const void* g = srcs[b] + (size_t)row * KDIM + kb * 8;
                cp_async16(sb + b * BUF_B + SW128(row * 128 + kb * 16), g);
            }
        }
    };

    float acc[4][4][4];                 // [mf][nf][4]
#pragma unroll
    for (int i = 0; i < 4; i++)
#pragma unroll
        for (int j = 0; j < 4; j++)
#pragma unroll
            for (int q = 0; q < 4; q++) acc[i][j][q] = 0.f;

    load_stage(0, 0);
    CP_COMMIT();

    for (int c = 0; c < NSTG; ++c) {
        if (c + 1 < NSTG) { load_stage((c + 1) & 1, c + 1); CP_COMMIT(); }
        if (c + 1 < NSTG) { CP_WAIT(1); } else { CP_WAIT(0); }
        __syncthreads();

        const uint32_t sb = sbase + (uint32_t)((c & 1) * STAGE_B);
        const uint32_t sAh = sb;
        const uint32_t sAl = sb + BUF_B;
        const uint32_t sBh = sb + 2 * BUF_B;
        const uint32_t sBl = sb + 3 * BUF_B;

#pragma unroll
        for (int s = 0; s < 4; ++s) {   // k16 steps
            // A fragments (hi, lo): rows wm0 + mf*16 + (lane&15), kblock 2s + (lane>>4)
            uint32_t ah[4][4], al[4][4];
            {
                const int arow = (lane & 15);
                const int akb  = 2 * s + (lane >> 4);
#pragma unroll
                for (int mf = 0; mf < 4; ++mf) {
                    const uint32_t off = SW128((uint32_t)(wm0 + mf * 16 + arow) * 128 + akb * 16);
                    ldsm_x4(ah[mf][0], ah[mf][1], ah[mf][2], ah[mf][3], sAh + off);
                    ldsm_x4(al[mf][0], al[mf][1], al[mf][2], al[mf][3], sAl + off);
                }
            }
            // B fragments (hi, lo): one x4 covers n16 x k16 -> two n8 frags
            uint32_t bh[4][2], bl[4][2];
            {
                const int brow = (lane & 7) + ((lane >> 4) & 1) * 8;
                const int bkb  = 2 * s + ((lane >> 3) & 1);
#pragma unroll
                for (int nf16 = 0; nf16 < 2; ++nf16) {
                    const uint32_t off = SW128((uint32_t)(wn0 + nf16 * 16 + brow) * 128 + bkb * 16);
                    ldsm_x4(bh[nf16*2][0], bh[nf16*2][1], bh[nf16*2+1][0], bh[nf16*2+1][1], sBh + off);
                    ldsm_x4(bl[nf16*2][0], bl[nf16*2][1], bl[nf16*2+1][0], bl[nf16*2+1][1], sBl + off);
                }
            }
#pragma unroll
            for (int mf = 0; mf < 4; ++mf)
#pragma unroll
                for (int nf = 0; nf < 4; ++nf) {
                    float* C = acc[mf][nf];
                    mma_bf16(C[0], C[1], C[2], C[3],
                             ah[mf][0], ah[mf][1], ah[mf][2], ah[mf][3],
                             bh[nf][0], bh[nf][1]);
                    mma_bf16(C[0], C[1], C[2], C[3],
                             ah[mf][0], ah[mf][1], ah[mf][2], ah[mf][3],
                             bl[nf][0], bl[nf][1]);
                    mma_bf16(C[0], C[1], C[2], C[3],
                             al[mf][0], al[mf][1], al[mf][2], al[mf][3],
                             bh[nf][0], bh[nf][1]);
                }
        }
        __syncthreads();
    }

    // ---- epilogue: accum -> padded smem stage -> coalesced float4 stores
    float* stage = (float*)smem;      // 128 x EPAD floats = 67584 B (fits in GSMEM)
    {
        const int g = lane >> 2;
        const int t = lane & 3;
#pragma unroll
        for (int mf = 0; mf < 4; ++mf) {
            const int r0 = wm0 + mf * 16 + g;
#pragma unroll
            for (int nf = 0; nf < 4; ++nf) {
                const int col = wn0 + nf * 8 + 2 * t;
                float* C = acc[mf][nf];
                stage[r0 * EPAD + col]           = C[0];
                stage[r0 * EPAD + col + 1]       = C[1];
                stage[(r0 + 8) * EPAD + col]     = C[2];
                stage[(r0 + 8) * EPAD + col + 1] = C[3];
            }
        }
    }
    __syncthreads();
#pragma unroll
    for (int i = 0; i < 16; ++i) {
        const int lin = i * 256 + tid;          // 0..4095
        const int r   = lin >> 5;
        const int c4  = (lin & 31) * 4;
        float4 v;
        v.x = stage[r * EPAD + c4 + 0];
        v.y = stage[r * EPAD + c4 + 1];
        v.z = stage[r * EPAD + c4 + 2];
        v.w = stage[r * EPAD + c4 + 3];
        *(float4*)(g_U + (size_t)(m0 + r) * NDIM + n0 + c4) = v;
    }
}

// ---------------------------------------------------------------------------
// Scan: one thread per (b,d) channel, 16-deep double-buffered prefetch.
// ---------------------------------------------------------------------------
__device__ __forceinline__ float sigmoidf_fast(float z)
{
    return __fdividef(1.f, 1.f + __expf(-z));
}

__global__ __launch_bounds__(128)
void sru_scan_kernel(const float* __restrict__ x,
                     const float* __restrict__ wc,
                     const float* __restrict__ bias,
                     float* __restrict__ out)
{
    const int tid = blockIdx.x * 128 + threadIdx.x;   // b*D + d
    const int d = tid & (DDIM - 1);

    const float wcf = wc[d];
    const float wcr = wc[DDIM + d];
    const float bf = bias[d];
    const float br = bias[DDIM + d];

    const float* __restrict__ U = g_U;
    const size_t stride = (size_t)BDIM * DDIM;   // 16384
    float c = 0.f;

    const int P = 16;
    float pu0[P], pu1[P], pu2[P], px[P];
#pragma unroll
    for (int i = 0; i < P; i++) {
        const size_t a = (size_t)tid + (size_t)i * stride;
        pu0[i] = U[3*a]; pu1[i] = U[3*a+1]; pu2[i] = U[3*a+2]; px[i] = x[a];
    }

    for (int l0 = 0; l0 < LDIM; l0 += P) {
        float nu0[P], nu1[P], nu2[P], nx[P];
        const bool more = (l0 + P < LDIM);
        if (more) {
            const size_t nb = (size_t)tid + (size_t)(l0 + P) * stride;
#pragma unroll
            for (int i = 0; i < P; i++) {
                const size_t a = nb + (size_t)i * stride;
                nu0[i] = U[3*a]; nu1[i] = U[3*a+1]; nu2[i] = U[3*a+2]; nx[i] = x[a];
            }
        }
#pragma unroll
        for (int i = 0; i < P; i++) {
            const float zf = fmaf(wcf, c, pu1[i] + bf);
            const float fg = sigmoidf_fast(zf);
            const float zr = fmaf(wcr, c, pu2[i] + br);
            const float rg = sigmoidf_fast(zr);
            c = fmaf(fg, c - pu0[i], pu0[i]);
            const float h = fmaf(rg, c - px[i], px[i]);
            out[(size_t)tid + (size_t)(l0 + i) * stride] = h;
        }
        if (more) {
#pragma unroll
            for (int i = 0; i < P; i++) {
                pu0[i] = nu0[i]; pu1[i] = nu1[i]; pu2[i] = nu2[i]; px[i] = nx[i];
            }
        }
    }

    out[(size_t)LDIM * stride + tid] = c;
}

// ---------------------------------------------------------------------------
extern "C" void kernel_launch(void* const* d_in, const int* in_sizes, int n_in,
                              void* d_out, int out_size)
{
    const float* x    = (const float*)d_in[0];   // (L,B,D)
    const float* W    = (const float*)d_in[1];   // (D, 3D)
    const float* wc   = (const float*)d_in[2];   // (2D,)
    const float* bias = (const float*)d_in[3];   // (2D,)
    float* out = (float*)d_out;

    cudaFuncSetAttribute(sru_gemm_hmma, cudaFuncAttributeMaxDynamicSharedMemorySize, GSMEM);

    convert_x_kernel<<<(MDIM * KDIM / 4) / 256, 256>>>(x);
    convert_w_kernel<<<(KDIM * NDIM) / 256, 256>>>(W);

    dim3 ggrid(NDIM / 128, MDIM / 128);          // (12, 512)
    sru_gemm_hmma<<<ggrid, 256, GSMEM>>>();

    sru_scan_kernel<<<(BDIM * DDIM) / 128, 128>>>(x, wc, bias, out);
}

// round 6
// speedup vs baseline: 4.5279x; 2.7291x over previous
#include <cuda_runtime.h>
#include <cuda_fp16.h>
#include <cstdint>

#define LDIM 2048
#define BDIM 32
#define DDIM 512
#define MDIM (LDIM * BDIM)   // 65536
#define NDIM (DDIM * 3)      // 1536
#define KDIM DDIM            // 512

// ---------------------------------------------------------------------------
// Device scratch
// ---------------------------------------------------------------------------
__device__ float  g_U4[(size_t)MDIM * 2048];           // [m][d] = (u0,u1,u2,pad), 512 MB
__device__ __half g_Ah[(size_t)MDIM * KDIM];           // x fp16, 64 MB
__device__ __half g_Bh[(size_t)NDIM * KDIM];           // W^T fp16 [o][k], 1.5 MB

__device__ __forceinline__ uint32_t smem_u32(const void* p) {
    uint32_t a;
    asm("{ .reg .u64 t; cvta.to.shared.u64 t, %1; cvt.u32.u64 %0, t; }" : "=r"(a) : "l"(p));
    return a;
}
#define SW128(o) ((o) ^ (((o) >> 3) & 0x70))

__device__ __forceinline__ void cp_async16(uint32_t saddr, const void* gaddr) {
    asm volatile("cp.async.cg.shared.global [%0], [%1], 16;" :: "r"(saddr), "l"(gaddr) : "memory");
}
__device__ __forceinline__ void cp_async4(uint32_t saddr, const void* gaddr) {
    asm volatile("cp.async.ca.shared.global [%0], [%1], 4;" :: "r"(saddr), "l"(gaddr) : "memory");
}
#define CP_COMMIT() asm volatile("cp.async.commit_group;" ::: "memory")
#define CP_WAIT(n)  asm volatile("cp.async.wait_group %0;" :: "n"(n) : "memory")

__device__ __forceinline__ void ldsm_x4(uint32_t& r0, uint32_t& r1, uint32_t& r2, uint32_t& r3, uint32_t addr) {
    asm volatile("ldmatrix.sync.aligned.m8n8.x4.shared.b16 {%0,%1,%2,%3}, [%4];"
                 : "=r"(r0), "=r"(r1), "=r"(r2), "=r"(r3) : "r"(addr));
}
__device__ __forceinline__ void mma_f16(float& c0, float& c1, float& c2, float& c3,
                                        uint32_t a0, uint32_t a1, uint32_t a2, uint32_t a3,
                                        uint32_t b0, uint32_t b1) {
    asm volatile("mma.sync.aligned.m16n8k16.row.col.f32.f16.f16.f32 "
                 "{%0,%1,%2,%3}, {%4,%5,%6,%7}, {%8,%9}, {%0,%1,%2,%3};"
                 : "+f"(c0), "+f"(c1), "+f"(c2), "+f"(c3)
                 : "r"(a0), "r"(a1), "r"(a2), "r"(a3), "r"(b0), "r"(b1));
}
__device__ __forceinline__ float ex2f(float z) { float r; asm("ex2.approx.f32 %0, %1;" : "=f"(r) : "f"(z)); return r; }
__device__ __forceinline__ float rcpf(float z) { float r; asm("rcp.approx.f32 %0, %1;" : "=f"(r) : "f"(z)); return r; }

// ---------------------------------------------------------------------------
// Converts
// ---------------------------------------------------------------------------
__global__ __launch_bounds__(256)
void convert_x_kernel(const float* __restrict__ x)
{
    const size_t i = (size_t)blockIdx.x * 256 + threadIdx.x;   // 8 floats per thread
    const float4 v0 = ((const float4*)x)[2 * i];
    const float4 v1 = ((const float4*)x)[2 * i + 1];
    __half2 h[4];
    h[0] = __floats2half2_rn(v0.x, v0.y);
    h[1] = __floats2half2_rn(v0.z, v0.w);
    h[2] = __floats2half2_rn(v1.x, v1.y);
    h[3] = __floats2half2_rn(v1.z, v1.w);
    ((uint4*)g_Ah)[i] = *(const uint4*)h;
}

__global__ __launch_bounds__(256)
void convert_w_kernel(const float* __restrict__ W)
{
    const int idx = blockIdx.x * 256 + threadIdx.x;   // < KDIM*NDIM
    const int k = idx / NDIM;
    const int o = idx % NDIM;
    g_Bh[(size_t)o * KDIM + k] = __float2half_rn(W[idx]);
}

// ---------------------------------------------------------------------------
// fp16 HMMA GEMM, single pass. 128x128x64 tiles, cp.async 2-stage pipeline.
// Epilogue scatters into padded-U layout: float index m*2048 + 4*(o/3) + o%3.
// ---------------------------------------------------------------------------
#define BK 64
#define NSTG (KDIM / BK)            // 8
#define BUF_B (128 * BK * 2)        // 16384 bytes per operand buffer
#define STAGE_B (2 * BUF_B)         // A, B
#define EPAD 132
#define GSMEM (128 * EPAD * 4)      // 67584 >= 2*STAGE_B (65536)

__global__ __launch_bounds__(256, 2)
void sru_gemm_hmma()
{
    extern __shared__ char smem[];
    const uint32_t sbase = smem_u32(smem);
    const int tid = threadIdx.x;
    const int n0 = blockIdx.x * 128;
    const int m0 = blockIdx.y * 128;

    const int wid = tid >> 5;
    const int lane = tid & 31;
    const int wm0 = (wid & 1) * 64;
    const int wn0 = (wid >> 1) * 32;

    auto load_stage = [&](int stg, int c) {
        const uint32_t sb = sbase + (uint32_t)(stg * STAGE_B);
        const int k0 = c * BK;
        const __half* srcA = g_Ah + (size_t)m0 * KDIM + k0;
        const __half* srcB = g_Bh + (size_t)n0 * KDIM + k0;
#pragma unroll
        for (int j = 0; j < 4; ++j) {
            const int slot = j * 256 + tid;    // 0..1023
            const int row  = slot >> 3;
            const int kb   = slot & 7;
            cp_async16(sb + SW128(row * 128 + kb * 16), srcA + (size_t)row * KDIM + kb * 8);
            cp_async16(sb + BUF_B + SW128(row * 128 + kb * 16), srcB + (size_t)row * KDIM + kb * 8);
        }
    };

    float acc[4][4][4];
#pragma unroll
    for (int i = 0; i < 4; i++)
#pragma unroll
        for (int j = 0; j < 4; j++)
#pragma unroll
            for (int q = 0; q < 4; q++) acc[i][j][q] = 0.f;

    load_stage(0, 0);
    CP_COMMIT();

    for (int c = 0; c < NSTG; ++c) {
        if (c + 1 < NSTG) { load_stage((c + 1) & 1, c + 1); CP_COMMIT(); CP_WAIT(1); }
        else              { CP_WAIT(0); }
        __syncthreads();

        const uint32_t sb = sbase + (uint32_t)((c & 1) * STAGE_B);
        const uint32_t sA = sb;
        const uint32_t sB = sb + BUF_B;

#pragma unroll
        for (int s = 0; s < 4; ++s) {   // k16 steps
            uint32_t ah[4][4];
            {
                const int arow = (lane & 15);
                const int akb  = 2 * s + (lane >> 4);
#pragma unroll
                for (int mf = 0; mf < 4; ++mf) {
                    const uint32_t off = SW128((uint32_t)(wm0 + mf * 16 + arow) * 128 + akb * 16);
                    ldsm_x4(ah[mf][0], ah[mf][1], ah[mf][2], ah[mf][3], sA + off);
                }
            }
            uint32_t bh[4][2];
            {
                const int brow = (lane & 7) + ((lane >> 4) & 1) * 8;
                const int bkb  = 2 * s + ((lane >> 3) & 1);
#pragma unroll
                for (int nf16 = 0; nf16 < 2; ++nf16) {
                    const uint32_t off = SW128((uint32_t)(wn0 + nf16 * 16 + brow) * 128 + bkb * 16);
                    ldsm_x4(bh[nf16*2][0], bh[nf16*2][1], bh[nf16*2+1][0], bh[nf16*2+1][1], sB + off);
                }
            }
#pragma unroll
            for (int mf = 0; mf < 4; ++mf)
#pragma unroll
                for (int nf = 0; nf < 4; ++nf) {
                    float* C = acc[mf][nf];
                    mma_f16(C[0], C[1], C[2], C[3],
                            ah[mf][0], ah[mf][1], ah[mf][2], ah[mf][3],
                            bh[nf][0], bh[nf][1]);
                }
        }
        __syncthreads();
    }

    // ---- epilogue: accum -> padded smem stage -> scatter into g_U4
    float* stage = (float*)smem;
    {
        const int g = lane >> 2;
        const int t = lane & 3;
#pragma unroll
        for (int mf = 0; mf < 4; ++mf) {
            const int r0 = wm0 + mf * 16 + g;
#pragma unroll
            for (int nf = 0; nf < 4; ++nf) {
                const int col = wn0 + nf * 8 + 2 * t;
                float* C = acc[mf][nf];
                stage[r0 * EPAD + col]           = C[0];
                stage[r0 * EPAD + col + 1]       = C[1];
                stage[(r0 + 8) * EPAD + col]     = C[2];
                stage[(r0 + 8) * EPAD + col + 1] = C[3];
            }
        }
    }
    __syncthreads();
#pragma unroll
    for (int it = 0; it < 64; ++it) {
        const int lin = it * 256 + tid;          // 0..16383
        const int r = lin >> 7;
        const int o = lin & 127;
        const int go = n0 + o;
        const int dd = go / 3;
        const int jj = go - 3 * dd;
        g_U4[(size_t)(m0 + r) * 2048 + 4 * dd + jj] = stage[r * EPAD + o];
    }
}

// ---------------------------------------------------------------------------
// Scan: 64-thread CTAs x 256 blocks, cp.async smem ring (16 stages).
// ---------------------------------------------------------------------------
#define SSTG 16
#define SCAN_T 64
#define SCAN_SMEM (SSTG * SCAN_T * 20)   // 20 KB

__global__ __launch_bounds__(SCAN_T)
void sru_scan_kernel(const float* __restrict__ x,
                     const float* __restrict__ wc,
                     const float* __restrict__ bias,
                     float* __restrict__ out)
{
    extern __shared__ char ssm[];
    const uint32_t sbase = smem_u32(ssm);
    const uint32_t xoff = SSTG * SCAN_T * 16;
    const float4* ringu = (const float4*)ssm;
    const float*  ringx = (const float*)(ssm + xoff);

    const int t = threadIdx.x;
    const int tid = blockIdx.x * SCAN_T + t;   // b*D + d
    const int d = tid & (DDIM - 1);

    const float LOG2E = 1.4426950408889634f;
    const float wcf2 = -wc[d] * LOG2E;
    const float wcr2 = -wc[DDIM + d] * LOG2E;
    const float bf = bias[d];
    const float br = bias[DDIM + d];

    const size_t stride = (size_t)BDIM * DDIM;   // 16384
    const float* U = g_U4 + (size_t)tid * 4;

    // prologue: fill ring
#pragma unroll
    for (int i = 0; i < SSTG; ++i) {
        cp_async16(sbase + (i * SCAN_T + t) * 16, U + (size_t)i * stride * 4);
        cp_async4(sbase + xoff + (i * SCAN_T + t) * 4, x + (size_t)i * stride + tid);
        CP_COMMIT();
    }

    float c = 0.f;
    for (int l = 0; l < LDIM; ++l) {
        CP_WAIT(SSTG - 1);
        const int st = l & (SSTG - 1);
        const float4 u = ringu[st * SCAN_T + t];
        const float xv = ringx[st * SCAN_T + t];

        const float t1 = -(u.y + bf) * LOG2E;
        const float t2 = -(u.z + br) * LOG2E;
        const float fg = rcpf(1.f + ex2f(fmaf(wcf2, c, t1)));
        const float rg = rcpf(1.f + ex2f(fmaf(wcr2, c, t2)));
        c = fmaf(fg, c - u.x, u.x);
        const float h = fmaf(rg, c - xv, xv);
        out[(size_t)l * stride + tid] = h;

        const int nl = l + SSTG;
        if (nl < LDIM) {
            cp_async16(sbase + (st * SCAN_T + t) * 16, U + (size_t)nl * stride * 4);
            cp_async4(sbase + xoff + (st * SCAN_T + t) * 4, x + (size_t)nl * stride + tid);
        }
        CP_COMMIT();
    }

    out[(size_t)LDIM * stride + tid] = c;
}

// ---------------------------------------------------------------------------
extern "C" void kernel_launch(void* const* d_in, const int* in_sizes, int n_in,
                              void* d_out, int out_size)
{
    const float* x    = (const float*)d_in[0];   // (L,B,D)
    const float* W    = (const float*)d_in[1];   // (D, 3D)
    const float* wc   = (const float*)d_in[2];   // (2D,)
    const float* bias = (const float*)d_in[3];   // (2D,)
    float* out = (float*)d_out;

    cudaFuncSetAttribute(sru_gemm_hmma, cudaFuncAttributeMaxDynamicSharedMemorySize, GSMEM);

    convert_x_kernel<<<(MDIM * KDIM / 8) / 256, 256>>>(x);
    convert_w_kernel<<<(KDIM * NDIM) / 256, 256>>>(W);

    dim3 ggrid(NDIM / 128, MDIM / 128);          // (12, 512)
    sru_gemm_hmma<<<ggrid, 256, GSMEM>>>();

    sru_scan_kernel<<<(BDIM * DDIM) / SCAN_T, SCAN_T, SCAN_SMEM>>>(x, wc, bias, out);
}

// round 8
// speedup vs baseline: 4.6136x; 1.0189x over previous
#include <cuda_runtime.h>
#include <cuda_fp16.h>
#include <cstdint>

#define LDIM 2048
#define BDIM 32
#define DDIM 512
#define MDIM (LDIM * BDIM)   // 65536
#define NDIM (DDIM * 3)      // 1536
#define KDIM DDIM            // 512

// ---------------------------------------------------------------------------
// Device scratch
// ---------------------------------------------------------------------------
__device__ uint2  g_U8[(size_t)MDIM * DDIM];   // {fp32 u0, half u1, half u2} = 8B, 256 MB
__device__ __half g_Ah[(size_t)MDIM * KDIM];   // x fp16, 64 MB
__device__ __half g_Bh[(size_t)NDIM * KDIM];   // W^T fp16 [o][k], 1.5 MB

__device__ __forceinline__ uint32_t smem_u32(const void* p) {
    uint32_t a;
    asm("{ .reg .u64 t; cvta.to.shared.u64 t, %1; cvt.u32.u64 %0, t; }" : "=r"(a) : "l"(p));
    return a;
}
#define SW128(o) ((o) ^ (((o) >> 3) & 0x70))

__device__ __forceinline__ void cp_async16(uint32_t saddr, const void* gaddr) {
    asm volatile("cp.async.cg.shared.global [%0], [%1], 16;" :: "r"(saddr), "l"(gaddr) : "memory");
}
__device__ __forceinline__ void cp_async8(uint32_t saddr, const void* gaddr) {
    asm volatile("cp.async.ca.shared.global [%0], [%1], 8;" :: "r"(saddr), "l"(gaddr) : "memory");
}
__device__ __forceinline__ void cp_async4(uint32_t saddr, const void* gaddr) {
    asm volatile("cp.async.ca.shared.global [%0], [%1], 4;" :: "r"(saddr), "l"(gaddr) : "memory");
}
#define CP_COMMIT() asm volatile("cp.async.commit_group;" ::: "memory")
#define CP_WAIT(n)  asm volatile("cp.async.wait_group %0;" :: "n"(n) : "memory")

__device__ __forceinline__ void ldsm_x4(uint32_t& r0, uint32_t& r1, uint32_t& r2, uint32_t& r3, uint32_t addr) {
    asm volatile("ldmatrix.sync.aligned.m8n8.x4.shared.b16 {%0,%1,%2,%3}, [%4];"
                 : "=r"(r0), "=r"(r1), "=r"(r2), "=r"(r3) : "r"(addr));
}
__device__ __forceinline__ void mma_f16(float& c0, float& c1, float& c2, float& c3,
                                        uint32_t a0, uint32_t a1, uint32_t a2, uint32_t a3,
                                        uint32_t b0, uint32_t b1) {
    asm volatile("mma.sync.aligned.m16n8k16.row.col.f32.f16.f16.f32 "
                 "{%0,%1,%2,%3}, {%4,%5,%6,%7}, {%8,%9}, {%0,%1,%2,%3};"
                 : "+f"(c0), "+f"(c1), "+f"(c2), "+f"(c3)
                 : "r"(a0), "r"(a1), "r"(a2), "r"(a3), "r"(b0), "r"(b1));
}
__device__ __forceinline__ float ex2f(float z) { float r; asm("ex2.approx.f32 %0, %1;" : "=f"(r) : "f"(z)); return r; }
__device__ __forceinline__ float rcpf(float z) { float r; asm("rcp.approx.f32 %0, %1;" : "=f"(r) : "f"(z)); return r; }

// ---------------------------------------------------------------------------
// Converts
// ---------------------------------------------------------------------------
__global__ __launch_bounds__(256)
void convert_x_kernel(const float* __restrict__ x)
{
    const size_t i = (size_t)blockIdx.x * 256 + threadIdx.x;   // 8 floats / thread
    const float4 v0 = ((const float4*)x)[2 * i];
    const float4 v1 = ((const float4*)x)[2 * i + 1];
    __half2 h[4];
    h[0] = __floats2half2_rn(v0.x, v0.y);
    h[1] = __floats2half2_rn(v0.z, v0.w);
    h[2] = __floats2half2_rn(v1.x, v1.y);
    h[3] = __floats2half2_rn(v1.z, v1.w);
    ((uint4*)g_Ah)[i] = *(const uint4*)h;
}

__global__ __launch_bounds__(256)
void convert_w_kernel(const float* __restrict__ W)
{
    const int idx = blockIdx.x * 256 + threadIdx.x;   // < KDIM*NDIM
    const int k = idx / NDIM;
    const int o = idx % NDIM;
    g_Bh[(size_t)o * KDIM + k] = __float2half_rn(W[idx]);
}

// ---------------------------------------------------------------------------
// fp16 HMMA GEMM: 128x192x64 tiles, 3-stage cp.async pipeline, 8 warps (2x4).
// Epilogue packs (u0 fp32, u1 half, u2 half) -> 8B words, fully coalesced.
// ---------------------------------------------------------------------------
#define BM 128
#define BN 192
#define BK 64
#define NSTG (KDIM / BK)            // 8
#define ABUF_B (BM * BK * 2)        // 16384
#define BBUF_B (BN * BK * 2)        // 24576
#define STAGE_B (ABUF_B + BBUF_B)   // 40960
#define NPIPE 3
#define EP_P 196                    // epilogue stage row stride (floats)
#define EP_HB (64 * EP_P * 4)       // 50176 bytes (half-tile stage)
#define GSMEM (NPIPE * STAGE_B)     // 122880 (>= EP_HB)

__global__ __launch_bounds__(256)
void sru_gemm_hmma()
{
    extern __shared__ char smem[];
    const uint32_t sbase = smem_u32(smem);
    const int tid = threadIdx.x;
    const int n0 = blockIdx.x * BN;
    const int m0 = blockIdx.y * BM;

    const int wid = tid >> 5;
    const int lane = tid & 31;
    const int wmh = (wid & 1);          // m half (0/1)
    const int wm0 = wmh * 64;
    const int wn0 = (wid >> 1) * 48;

    auto load_stage = [&](int stg, int c) {
        const uint32_t sb = sbase + (uint32_t)(stg * STAGE_B);
        const int k0 = c * BK;
        const __half* srcA = g_Ah + (size_t)m0 * KDIM + k0;
        const __half* srcB = g_Bh + (size_t)n0 * KDIM + k0;
#pragma unroll
        for (int j = 0; j < 4; ++j) {               // A: 1024 uint4
            const int slot = j * 256 + tid;
            const int row  = slot >> 3;
            const int kb   = slot & 7;
            cp_async16(sb + SW128(row * 128 + kb * 16), srcA + (size_t)row * KDIM + kb * 8);
        }
#pragma unroll
        for (int j = 0; j < 6; ++j) {               // B: 1536 uint4
            const int slot = j * 256 + tid;
            const int row  = slot >> 3;
            const int kb   = slot & 7;
            cp_async16(sb + ABUF_B + SW128(row * 128 + kb * 16), srcB + (size_t)row * KDIM + kb * 8);
        }
    };

    float acc[4][6][4];
#pragma unroll
    for (int i = 0; i < 4; i++)
#pragma unroll
        for (int j = 0; j < 6; j++)
#pragma unroll
            for (int q = 0; q < 4; q++) acc[i][j][q] = 0.f;

    load_stage(0, 0); CP_COMMIT();
    load_stage(1, 1); CP_COMMIT();

    for (int c = 0; c < NSTG; ++c) {
        if (c + 2 < NSTG) load_stage((c + 2) % NPIPE, c + 2);
        CP_COMMIT();                    // empty group in tail keeps wait semantics
        CP_WAIT(2);
        __syncthreads();

        const uint32_t sb = sbase + (uint32_t)((c % NPIPE) * STAGE_B);
        const uint32_t sA = sb;
        const uint32_t sB = sb + ABUF_B;

#pragma unroll
        for (int s = 0; s < 4; ++s) {   // four k16 steps
            uint32_t ah[4][4];
            {
                const int arow = (lane & 15);
                const int akb  = 2 * s + (lane >> 4);
#pragma unroll
                for (int mf = 0; mf < 4; ++mf) {
                    const uint32_t off = SW128((uint32_t)(wm0 + mf * 16 + arow) * 128 + akb * 16);
                    ldsm_x4(ah[mf][0], ah[mf][1], ah[mf][2], ah[mf][3], sA + off);
                }
            }
            uint32_t bh[6][2];
            {
                const int brow = (lane & 7) + ((lane >> 4) & 1) * 8;
                const int bkb  = 2 * s + ((lane >> 3) & 1);
#pragma unroll
                for (int nf16 = 0; nf16 < 3; ++nf16) {
                    const uint32_t off = SW128((uint32_t)(wn0 + nf16 * 16 + brow) * 128 + bkb * 16);
                    ldsm_x4(bh[nf16*2][0], bh[nf16*2][1], bh[nf16*2+1][0], bh[nf16*2+1][1], sB + off);
                }
            }
#pragma unroll
            for (int mf = 0; mf < 4; ++mf)
#pragma unroll
                for (int nf = 0; nf < 6; ++nf) {
                    float* C = acc[mf][nf];
                    mma_f16(C[0], C[1], C[2], C[3],
                            ah[mf][0], ah[mf][1], ah[mf][2], ah[mf][3],
                            bh[nf][0], bh[nf][1]);
                }
        }
        __syncthreads();
    }

    // ---- epilogue in two 64-row halves: regs -> stage -> packed 8B stores
    float* stage = (float*)smem;              // 64 x EP_P floats
    const int d0 = blockIdx.x * 64;
#pragma unroll
    for (int h = 0; h < 2; ++h) {
        __syncthreads();
        if (wmh == h) {
            const int g = lane >> 2;
            const int t = lane & 3;
#pragma unroll
            for (int mf = 0; mf < 4; ++mf) {
                const int lr = mf * 16 + g;               // local row in half
#pragma unroll
                for (int nf = 0; nf < 6; ++nf) {
                    const int col = wn0 + nf * 8 + 2 * t;
                    float* C = acc[mf][nf];
                    stage[lr * EP_P + col]           = C[0];
                    stage[lr * EP_P + col + 1]       = C[1];
                    stage[(lr + 8) * EP_P + col]     = C[2];
                    stage[(lr + 8) * EP_P + col + 1] = C[3];
                }
            }
        }
        __syncthreads();
#pragma unroll
        for (int it = 0; it < 16; ++it) {
            const int lin = it * 256 + tid;   // 0..4095 : (row, d-col)
            const int lr = lin >> 6;
            const int dc = lin & 63;
            const float u0 = stage[lr * EP_P + 3 * dc];
            const float u1 = stage[lr * EP_P + 3 * dc + 1];
            const float u2 = stage[lr * EP_P + 3 * dc + 2];
            uint2 w;
            w.x = __float_as_uint(u0);
            const __half2 p = __floats2half2_rn(u1, u2);
            w.y = *(const uint32_t*)&p;
            g_U8[(size_t)(m0 + h * 64 + lr) * DDIM + d0 + dc] = w;
        }
    }
}

// ---------------------------------------------------------------------------
// Scan: 64-thread CTAs x 256 blocks, cp.async smem ring (16 stages).
// Ring entry: 8B packed U + 4B x.
// ---------------------------------------------------------------------------
#define SSTG 16
#define SCAN_T 64
#define SCAN_SMEM (SSTG * SCAN_T * 12)   // 12 KB

__global__ __launch_bounds__(SCAN_T)
void sru_scan_kernel(const float* __restrict__ x,
                     const float* __restrict__ wc,
                     const float* __restrict__ bias,
                     float* __restrict__ out)
{
    extern __shared__ char ssm[];
    const uint32_t sbase = smem_u32(ssm);
    const uint32_t xoff = SSTG * SCAN_T * 8;
    const uint2* ringu = (const uint2*)ssm;
    const float* ringx = (const float*)(ssm + xoff);

    const int t = threadIdx.x;
    const int tid = blockIdx.x * SCAN_T + t;   // b*D + d
    const int d = tid & (DDIM - 1);

    const float LOG2E = 1.4426950408889634f;
    const float wcf2 = -wc[d] * LOG2E;
    const float wcr2 = -wc[DDIM + d] * LOG2E;
    const float bf2 = -bias[d] * LOG2E;
    const float br2 = -bias[DDIM + d] * LOG2E;

    const size_t stride = (size_t)BDIM * DDIM;   // 16384
    const uint2* U = g_U8 + tid;

#pragma unroll
    for (int i = 0; i < SSTG; ++i) {
        cp_async8(sbase + (i * SCAN_T + t) * 8, U + (size_t)i * stride);
        cp_async4(sbase + xoff + (i * SCAN_T + t) * 4, x + (size_t)i * stride + tid);
        CP_COMMIT();
    }

    float c = 0.f;
    for (int l = 0; l < LDIM; ++l) {
        CP_WAIT(SSTG - 1);
        const int st = l & (SSTG - 1);
        const uint2 w = ringu[st * SCAN_T + t];
        const float xv = ringx[st * SCAN_T + t];
        const float u0 = __uint_as_float(w.x);
        const __half2 p = *(const __half2*)&w.y;
        const float2 u12 = __half22float2(p);

        const float fg = rcpf(1.f + ex2f(fmaf(wcf2, c, fmaf(-LOG2E, u12.x, bf2))));
        const float rg = rcpf(1.f + ex2f(fmaf(wcr2, c, fmaf(-LOG2E, u12.y, br2))));
        c = fmaf(fg, c - u0, u0);
        const float h = fmaf(rg, c - xv, xv);
        out[(size_t)l * stride + tid] = h;

        const int nl = l + SSTG;
        if (nl < LDIM) {
            cp_async8(sbase + (st * SCAN_T + t) * 8, U + (size_t)nl * stride);
            cp_async4(sbase + xoff + (st * SCAN_T + t) * 4, x + (size_t)nl * stride + tid);
        }
        CP_COMMIT();
    }

    out[(size_t)LDIM * stride + tid] = c;
}

// ---------------------------------------------------------------------------
extern "C" void kernel_launch(void* const* d_in, const int* in_sizes, int n_in,
                              void* d_out, int out_size)
{
    const float* x    = (const float*)d_in[0];   // (L,B,D)
    const float* W    = (const float*)d_in[1];   // (D, 3D)
    const float* wc   = (const float*)d_in[2];   // (2D,)
    const float* bias = (const float*)d_in[3];   // (2D,)
    float* out = (float*)d_out;

    cudaFuncSetAttribute(sru_gemm_hmma, cudaFuncAttributeMaxDynamicSharedMemorySize, GSMEM);

    convert_x_kernel<<<(MDIM * KDIM / 8) / 256, 256>>>(x);
    convert_w_kernel<<<(KDIM * NDIM) / 256, 256>>>(W);

    dim3 ggrid(NDIM / BN, MDIM / BM);            // (8, 512)
    sru_gemm_hmma<<<ggrid, 256, GSMEM>>>();

    sru_scan_kernel<<<(BDIM * DDIM) / SCAN_T, SCAN_T, SCAN_SMEM>>>(x, wc, bias, out);
}

// round 9
// speedup vs baseline: 5.5622x; 1.2056x over previous
#include <cuda_runtime.h>
#include <cuda_fp16.h>
#include <cstdint>

#define LDIM 2048
#define BDIM 32
#define DDIM 512
#define MDIM (LDIM * BDIM)   // 65536
#define NDIM (DDIM * 3)      // 1536
#define KDIM DDIM            // 512

#define BM 128
#define BN 192
#define BK 64
#define NTILES_N 8
#define NTILES_M 512
#define TOT_TILES (NTILES_M * NTILES_N)   // 4096
#define NGEMM_CTAS 148

// ---------------------------------------------------------------------------
// Device scratch
// ---------------------------------------------------------------------------
__device__ uint2  g_U8[(size_t)MDIM * DDIM];   // {fp32 u0, half u1, half u2}, 256 MB
__device__ __half g_Ah[(size_t)MDIM * KDIM];   // x fp16
__device__ __half g_Bh[(size_t)NDIM * KDIM];   // W^T fp16 [o][k]
__device__ int    g_cnt[NTILES_M];             // per-m-tile completion counters

__device__ __forceinline__ uint32_t smem_u32(const void* p) {
    uint32_t a;
    asm("{ .reg .u64 t; cvta.to.shared.u64 t, %1; cvt.u32.u64 %0, t; }" : "=r"(a) : "l"(p));
    return a;
}
#define SW128(o) ((o) ^ (((o) >> 3) & 0x70))

__device__ __forceinline__ void cp_async16(uint32_t saddr, const void* gaddr) {
    asm volatile("cp.async.cg.shared.global [%0], [%1], 16;" :: "r"(saddr), "l"(gaddr) : "memory");
}
__device__ __forceinline__ void cp_async8(uint32_t saddr, const void* gaddr) {
    asm volatile("cp.async.ca.shared.global [%0], [%1], 8;" :: "r"(saddr), "l"(gaddr) : "memory");
}
__device__ __forceinline__ void cp_async4(uint32_t saddr, const void* gaddr) {
    asm volatile("cp.async.ca.shared.global [%0], [%1], 4;" :: "r"(saddr), "l"(gaddr) : "memory");
}
#define CP_COMMIT() asm volatile("cp.async.commit_group;" ::: "memory")
#define CP_WAIT(n)  asm volatile("cp.async.wait_group %0;" :: "n"(n) : "memory")
#define BAR256()    asm volatile("bar.sync 1, 256;" ::: "memory")

__device__ __forceinline__ void ldsm_x4(uint32_t& r0, uint32_t& r1, uint32_t& r2, uint32_t& r3, uint32_t addr) {
    asm volatile("ldmatrix.sync.aligned.m8n8.x4.shared.b16 {%0,%1,%2,%3}, [%4];"
                 : "=r"(r0), "=r"(r1), "=r"(r2), "=r"(r3) : "r"(addr));
}
__device__ __forceinline__ void mma_f16(float& c0, float& c1, float& c2, float& c3,
                                        uint32_t a0, uint32_t a1, uint32_t a2, uint32_t a3,
                                        uint32_t b0, uint32_t b1) {
    asm volatile("mma.sync.aligned.m16n8k16.row.col.f32.f16.f16.f32 "
                 "{%0,%1,%2,%3}, {%4,%5,%6,%7}, {%8,%9}, {%0,%1,%2,%3};"
                 : "+f"(c0), "+f"(c1), "+f"(c2), "+f"(c3)
                 : "r"(a0), "r"(a1), "r"(a2), "r"(a3), "r"(b0), "r"(b1));
}
__device__ __forceinline__ float ex2f(float z) { float r; asm("ex2.approx.f32 %0, %1;" : "=f"(r) : "f"(z)); return r; }
__device__ __forceinline__ float rcpf(float z) { float r; asm("rcp.approx.f32 %0, %1;" : "=f"(r) : "f"(z)); return r; }

__device__ __forceinline__ int ld_cnt(const int* p) {
    int v;
    asm volatile("ld.global.cg.b32 %0, [%1];" : "=r"(v) : "l"(p));
    return v;
}

// ---------------------------------------------------------------------------
// Converts (+ counter reset in convert_w, which runs before the fused kernel)
// ---------------------------------------------------------------------------
__global__ __launch_bounds__(256)
void convert_x_kernel(const float* __restrict__ x)
{
    const size_t i = (size_t)blockIdx.x * 256 + threadIdx.x;
    const float4 v0 = ((const float4*)x)[2 * i];
    const float4 v1 = ((const float4*)x)[2 * i + 1];
    __half2 h[4];
    h[0] = __floats2half2_rn(v0.x, v0.y);
    h[1] = __floats2half2_rn(v0.z, v0.w);
    h[2] = __floats2half2_rn(v1.x, v1.y);
    h[3] = __floats2half2_rn(v1.z, v1.w);
    ((uint4*)g_Ah)[i] = *(const uint4*)h;
}

__global__ __launch_bounds__(256)
void convert_w_kernel(const float* __restrict__ W)
{
    const int idx = blockIdx.x * 256 + threadIdx.x;
    const int k = idx / NDIM;
    const int o = idx % NDIM;
    g_Bh[(size_t)o * KDIM + k] = __float2half_rn(W[idx]);
    if (blockIdx.x == 0 && threadIdx.x < 256) {
        g_cnt[threadIdx.x] = 0;
        g_cnt[threadIdx.x + 256] = 0;
    }
}

// ---------------------------------------------------------------------------
// Fused producer-consumer kernel.
//   warps 0-7 (tid<256): persistent HMMA GEMM over tiles bx, bx+148, ...
//   warps 8-11 (tid>=256, CTAs 0..127): SRU scan, gated on g_cnt.
// ---------------------------------------------------------------------------
#define ABUF_B (BM * BK * 2)        // 16384
#define BBUF_B (BN * BK * 2)        // 24576
#define STAGE_B (ABUF_B + BBUF_B)   // 40960
#define GSMEM (2 * STAGE_B)         // 81920
#define EP_P 196
#define SSTG 16                     // scan ring (steps)

__global__ __launch_bounds__(384, 1)
void sru_fused(const float* __restrict__ x,
               const float* __restrict__ wc,
               const float* __restrict__ bias,
               float* __restrict__ out)
{
    extern __shared__ char smem[];
    __shared__ uint2 s_ru[SSTG][128];
    __shared__ float s_rx[SSTG][128];

    const uint32_t sbase = smem_u32(smem);
    const int tid = threadIdx.x;
    const int bx = blockIdx.x;

    if (tid < 256) {
        // ================= GEMM producer =================
        const int wid = tid >> 5;
        const int lane = tid & 31;
        const int wmh = wid & 1;
        const int wm0 = wmh * 64;
        const int wn0 = (wid >> 1) * 48;

        const int myT = (TOT_TILES - bx + NGEMM_CTAS - 1) / NGEMM_CTAS;
        const int totq = myT * 8;

        auto issue = [&](int q) {
            if (q >= totq) return;
            const int tile = bx + (q >> 3) * NGEMM_CTAS;
            const int c = q & 7;
            const int m0 = (tile >> 3) * BM;
            const int n0 = (tile & 7) * BN;
            const int k0 = c * BK;
            const uint32_t sb = sbase + (uint32_t)((q & 1) * STAGE_B);
            const __half* srcA = g_Ah + (size_t)m0 * KDIM + k0;
            const __half* srcB = g_Bh + (size_t)n0 * KDIM + k0;
#pragma unroll
            for (int j = 0; j < 4; ++j) {               // A: 1024 uint4
                const int slot = j * 256 + tid;
                const int row  = slot >> 3;
                const int kb   = slot & 7;
                cp_async16(sb + SW128(row * 128 + kb * 16), srcA + (size_t)row * KDIM + kb * 8);
            }
#pragma unroll
            for (int j = 0; j < 6; ++j) {               // B: 1536 uint4
                const int slot = j * 256 + tid;
                const int row  = slot >> 3;
                const int kb   = slot & 7;
                cp_async16(sb + ABUF_B + SW128(row * 128 + kb * 16), srcB + (size_t)row * KDIM + kb * 8);
            }
        };

        float acc[4][6][4];
#pragma unroll
        for (int i = 0; i < 4; i++)
#pragma unroll
            for (int j = 0; j < 6; j++)
#pragma unroll
                for (int q = 0; q < 4; q++) acc[i][j][q] = 0.f;

        issue(0); CP_COMMIT();

        for (int q = 0; q < totq; ++q) {
            issue(q + 1); CP_COMMIT();
            CP_WAIT(1);
            BAR256();

            const uint32_t sb = sbase + (uint32_t)((q & 1) * STAGE_B);
            const uint32_t sA = sb;
            const uint32_t sB = sb + ABUF_B;

#pragma unroll
            for (int s = 0; s < 4; ++s) {
                uint32_t ah[4][4];
                {
                    const int arow = (lane & 15);
                    const int akb  = 2 * s + (lane >> 4);
#pragma unroll
                    for (int mf = 0; mf < 4; ++mf) {
                        const uint32_t off = SW128((uint32_t)(wm0 + mf * 16 + arow) * 128 + akb * 16);
                        ldsm_x4(ah[mf][0], ah[mf][1], ah[mf][2], ah[mf][3], sA + off);
                    }
                }
                uint32_t bh[6][2];
                {
                    const int brow = (lane & 7) + ((lane >> 4) & 1) * 8;
                    const int bkb  = 2 * s + ((lane >> 3) & 1);
#pragma unroll
                    for (int nf16 = 0; nf16 < 3; ++nf16) {
                        const uint32_t off = SW128((uint32_t)(wn0 + nf16 * 16 + brow) * 128 + bkb * 16);
                        ldsm_x4(bh[nf16*2][0], bh[nf16*2][1], bh[nf16*2+1][0], bh[nf16*2+1][1], sB + off);
                    }
                }
#pragma unroll
                for (int mf = 0; mf < 4; ++mf)
#pragma unroll
                    for (int nf = 0; nf < 6; ++nf) {
                        float* C = acc[mf][nf];
                        mma_f16(C[0], C[1], C[2], C[3],
                                ah[mf][0], ah[mf][1], ah[mf][2], ah[mf][3],
                                bh[nf][0], bh[nf][1]);
                    }
            }
            BAR256();

            if ((q & 7) == 7) {
                const int tile = bx + (q >> 3) * NGEMM_CTAS;
                const int m0 = (tile >> 3) * BM;
                const int d0 = (tile & 7) * 64;
                float* ep = (float*)(smem + (size_t)((q & 1) * STAGE_B));

#pragma unroll
                for (int q2 = 0; q2 < 4; ++q2) {
                    if (wmh == (q2 >> 1)) {
                        const int g = lane >> 2;
                        const int t4 = lane & 3;
#pragma unroll
                        for (int e = 0; e < 2; ++e) {
                            const int mf = 2 * (q2 & 1) + e;
                            const int lr = e * 16 + g;
#pragma unroll
                            for (int nf = 0; nf < 6; ++nf) {
                                const int col = wn0 + nf * 8 + 2 * t4;
                                float* C = acc[mf][nf];
                                ep[lr * EP_P + col]           = C[0];
                                ep[lr * EP_P + col + 1]       = C[1];
                                ep[(lr + 8) * EP_P + col]     = C[2];
                                ep[(lr + 8) * EP_P + col + 1] = C[3];
                            }
                        }
                    }
                    BAR256();
#pragma unroll
                    for (int it = 0; it < 8; ++it) {
                        const int lin = it * 256 + tid;    // 0..2047
                        const int lr = lin >> 6;
                        const int dc = lin & 63;
                        const float u0 = ep[lr * EP_P + 3 * dc];
                        const float u1 = ep[lr * EP_P + 3 * dc + 1];
                        const float u2 = ep[lr * EP_P + 3 * dc + 2];
                        uint2 w;
                        w.x = __float_as_uint(u0);
                        const __half2 p = __floats2half2_rn(u1, u2);
                        w.y = *(const uint32_t*)&p;
                        g_U8[(size_t)(m0 + q2 * 32 + lr) * DDIM + d0 + dc] = w;
                    }
                    BAR256();
                }

                __threadfence();
                BAR256();
                if (tid == 0) atomicAdd(&g_cnt[tile >> 3], 1);

#pragma unroll
                for (int i = 0; i < 4; i++)
#pragma unroll
                    for (int j = 0; j < 6; j++)
#pragma unroll
                        for (int p = 0; p < 4; p++) acc[i][j][p] = 0.f;
            }
        }
    } else {
        // ================= scan consumer =================
        if (bx >= 128) return;
        const int st = tid - 256;                 // 0..127
        const int ch = bx * 128 + st;             // b*D + d
        const int d = ch & (DDIM - 1);

        const float LOG2E = 1.4426950408889634f;
        const float wcf2 = -wc[d] * LOG2E;
        const float wcr2 = -wc[DDIM + d] * LOG2E;
        const float bf2 = -bias[d] * LOG2E;
        const float br2 = -bias[DDIM + d] * LOG2E;

        const uint32_t ru_base = smem_u32(&s_ru[0][0]);
        const uint32_t rx_base = smem_u32(&s_rx[0][0]);
        const size_t stride = (size_t)BDIM * DDIM;      // 16384

        auto wait_tile = [&](int mt) {
            while (ld_cnt(&g_cnt[mt]) < NTILES_N) __nanosleep(64);
        };

        // prologue: 4 groups of 4 steps
#pragma unroll
        for (int g = 0; g < 4; ++g) {
            wait_tile(g);
#pragma unroll
            for (int i = 0; i < 4; ++i) {
                const int l = g * 4 + i;
                cp_async8(ru_base + (uint32_t)((l & (SSTG - 1)) * 128 + st) * 8,
                          g_U8 + (size_t)l * stride + ch);
                cp_async4(rx_base + (uint32_t)((l & (SSTG - 1)) * 128 + st) * 4,
                          x + (size_t)l * stride + ch);
            }
            CP_COMMIT();
        }

        float c = 0.f;
        for (int gi = 0; gi < LDIM / 4; ++gi) {
            CP_WAIT(3);
#pragma unroll
            for (int i = 0; i < 4; ++i) {
                const int l = gi * 4 + i;
                const int slot = l & (SSTG - 1);
                const uint2 w = s_ru[slot][st];
                const float xv = s_rx[slot][st];
                const float u0 = __uint_as_float(w.x);
                const __half2 p = *(const __half2*)&w.y;
                const float2 u12 = __half22float2(p);

                const float fg = rcpf(1.f + ex2f(fmaf(wcf2, c, fmaf(-LOG2E, u12.x, bf2))));
                const float rg = rcpf(1.f + ex2f(fmaf(wcr2, c, fmaf(-LOG2E, u12.y, br2))));
                c = fmaf(fg, c - u0, u0);
                const float h = fmaf(rg, c - xv, xv);
                out[(size_t)l * stride + ch] = h;
            }
            const int ng = gi + 4;
            if (ng < LDIM / 4) {
                wait_tile(ng);
#pragma unroll
                for (int i = 0; i < 4; ++i) {
                    const int nl = ng * 4 + i;
                    cp_async8(ru_base + (uint32_t)((nl & (SSTG - 1)) * 128 + st) * 8,
                              g_U8 + (size_t)nl * stride + ch);
                    cp_async4(rx_base + (uint32_t)((nl & (SSTG - 1)) * 128 + st) * 4,
                              x + (size_t)nl * stride + ch);
                }
            }
            CP_COMMIT();
        }

        out[(size_t)LDIM * stride + ch] = c;
    }
}

// ---------------------------------------------------------------------------
extern "C" void kernel_launch(void* const* d_in, const int* in_sizes, int n_in,
                              void* d_out, int out_size)
{
    const float* x    = (const float*)d_in[0];   // (L,B,D)
    const float* W    = (const float*)d_in[1];   // (D, 3D)
    const float* wc   = (const float*)d_in[2];   // (2D,)
    const float* bias = (const float*)d_in[3];   // (2D,)
    float* out = (float*)d_out;

    cudaFuncSetAttribute(sru_fused, cudaFuncAttributeMaxDynamicSharedMemorySize, GSMEM);

    convert_x_kernel<<<(MDIM * KDIM / 8) / 256, 256>>>(x);
    convert_w_kernel<<<(KDIM * NDIM) / 256, 256>>>(W);   // also resets g_cnt

    sru_fused<<<NGEMM_CTAS, 384, GSMEM>>>(x, wc, bias, out);
}